// round 3
// baseline (speedup 1.0000x reference)
#include <cuda_runtime.h>
#include <math.h>

#define NMAX 50000
#define EMAX 800000

// ---------------- scratch (static device globals; no allocation) ----------------
__device__ __align__(16) int   g_src[EMAX];
__device__ __align__(16) int   g_dst[EMAX];
__device__ __align__(16) float g_xp1[NMAX * 128];
__device__ __align__(16) float g_num1[NMAX * 128];
__device__ __align__(16) float g_xp2[NMAX * 64];
__device__ __align__(16) float g_num2[NMAX * 64];
__device__ __align__(16) float g_as1[NMAX * 2], g_ad1[NMAX * 2], g_dn1[NMAX * 2];
__device__ __align__(16) float g_as2[NMAX * 2], g_ad2[NMAX * 2], g_dn2[NMAX * 2];
__device__ int g_is64;

template <int L> __device__ __forceinline__ float* XP()  { return L == 1 ? g_xp1  : g_xp2;  }
template <int L> __device__ __forceinline__ float* NUM() { return L == 1 ? g_num1 : g_num2; }
template <int L> __device__ __forceinline__ float* AS()  { return L == 1 ? g_as1  : g_as2;  }
template <int L> __device__ __forceinline__ float* AD()  { return L == 1 ? g_ad1  : g_ad2;  }
template <int L> __device__ __forceinline__ float* DN()  { return L == 1 ? g_dn1  : g_dn2;  }

__device__ __forceinline__ float lrelu(float x) { return x > 0.f ? x : 0.2f * x; }

// ---------------- kernels ----------------

// Detect edge_index dtype: int64 -> odd int32 words all zero (indices < 50000).
__global__ void k_detect(const int* __restrict__ ei32) {
    __shared__ int any;
    if (threadIdx.x == 0) any = 0;
    __syncthreads();
    for (int i = threadIdx.x; i < 2048; i += blockDim.x)
        if (ei32[2 * i + 1] != 0) any = 1;
    __syncthreads();
    if (threadIdx.x == 0) g_is64 = (any == 0) ? 1 : 0;
}

__global__ void k_convert(const void* __restrict__ ei, int E) {
    int e = blockIdx.x * blockDim.x + threadIdx.x;
    if (e >= E) return;
    if (g_is64) {
        const long long* p = (const long long*)ei;
        g_src[e] = (int)p[e];
        g_dst[e] = (int)p[(size_t)E + e];
    } else {
        const int* p = (const int*)ei;
        g_src[e] = p[e];
        g_dst[e] = p[(size_t)E + e];
    }
}

// Layer-1 GEMM: xp1[n,128] = x[n,128] @ W1[128,128]
__global__ void k_gemm1(const float* __restrict__ X, const float* __restrict__ W, int n) {
    constexpr int NCOL = 128;
    __shared__ float Ws[64][NCOL];
    __shared__ float Xs[32][64];
    int t  = threadIdx.x;
    int n0 = blockIdx.x * 32;
    float acc[32];
#pragma unroll
    for (int i = 0; i < 32; i++) acc[i] = 0.f;
    for (int kt = 0; kt < 128; kt += 64) {
        for (int k = 0; k < 64; k++) Ws[k][t] = W[(size_t)(kt + k) * NCOL + t];
        for (int i = t; i < 32 * 64; i += NCOL) {
            int nn = i >> 6, kk = i & 63;
            int row = n0 + nn;
            Xs[nn][kk] = (row < n) ? X[(size_t)row * 128 + kt + kk] : 0.f;
        }
        __syncthreads();
#pragma unroll 4
        for (int k = 0; k < 64; k++) {
            float w = Ws[k][t];
#pragma unroll
            for (int nn = 0; nn < 32; nn++) acc[nn] += Xs[nn][k] * w;
        }
        __syncthreads();
    }
#pragma unroll
    for (int nn = 0; nn < 32; nn++) {
        int row = n0 + nn;
        if (row < n) g_xp1[(size_t)row * NCOL + t] = acc[nn];
    }
}

// Layer-2 GEMM with fused finalize-1 on the X load:
//   Xval = elu(num1/dn1 + b1)
__global__ void k_gemm2(const float* __restrict__ W, const float* __restrict__ b1, int n) {
    constexpr int NCOL = 64;
    __shared__ float Ws[64][NCOL];
    __shared__ float Xs[32][64];
    int t  = threadIdx.x;
    int n0 = blockIdx.x * 32;
    float acc[32];
#pragma unroll
    for (int i = 0; i < 32; i++) acc[i] = 0.f;
    for (int kt = 0; kt < 128; kt += 64) {
        for (int k = 0; k < 64; k++) Ws[k][t] = W[(size_t)(kt + k) * NCOL + t];
        for (int i = t; i < 32 * 64; i += NCOL) {
            int nn = i >> 6, kk = i & 63;
            int row = n0 + nn;
            int col = kt + kk;
            float v = 0.f;
            if (row < n) {
                int head = col >> 6;
                float inv = 1.f / g_dn1[2 * (size_t)row + head];
                v = g_num1[(size_t)row * 128 + col] * inv + b1[col];
                v = v > 0.f ? v : expm1f(v);
            }
            Xs[nn][kk] = v;
        }
        __syncthreads();
#pragma unroll 4
        for (int k = 0; k < 64; k++) {
            float w = Ws[k][t];
#pragma unroll
            for (int nn = 0; nn < 32; nn++) acc[nn] += Xs[nn][k] * w;
        }
        __syncthreads();
    }
#pragma unroll
    for (int nn = 0; nn < 32; nn++) {
        int row = n0 + nn;
        if (row < n) g_xp2[(size_t)row * NCOL + t] = acc[nn];
    }
}

// Per-node: attention dots + self-loop init of denom and numerator (no segment max;
// logits are small so exp() without shift is safe and mathematically identical).
template <int L>
__global__ void k_att(const float* __restrict__ att_s, const float* __restrict__ att_d, int n) {
    constexpr int C = (L == 1) ? 128 : 64;
    constexpr int Q = C / 4;                 // float4 slots per row (32 or 16)
    const float* xp = XP<L>();
    float *as_ = AS<L>(), *ad_ = AD<L>(), *dn_ = DN<L>(), *num_ = NUM<L>();
    int w    = (int)((blockIdx.x * blockDim.x + threadIdx.x) >> 5);
    int lane = threadIdx.x & 31;
    if (w >= n) return;
    const float4* xr = (const float4*)(xp + (size_t)w * C);
    bool valid = lane < Q;
    float4 v = valid ? xr[lane] : make_float4(0.f, 0.f, 0.f, 0.f);
    int c = 4 * lane;
    float ps = 0.f, pd = 0.f;
    if (valid) {
        ps = v.x * att_s[c] + v.y * att_s[c + 1] + v.z * att_s[c + 2] + v.w * att_s[c + 3];
        pd = v.x * att_d[c] + v.y * att_d[c + 1] + v.z * att_d[c + 2] + v.w * att_d[c + 3];
    }
    int head = (c >= C / 2) ? 1 : 0;
    float s0 = head ? 0.f : ps, s1 = head ? ps : 0.f;
    float d0 = head ? 0.f : pd, d1 = head ? pd : 0.f;
#pragma unroll
    for (int o = 16; o; o >>= 1) {
        s0 += __shfl_xor_sync(0xffffffffu, s0, o);
        s1 += __shfl_xor_sync(0xffffffffu, s1, o);
        d0 += __shfl_xor_sync(0xffffffffu, d0, o);
        d1 += __shfl_xor_sync(0xffffffffu, d1, o);
    }
    float ee0 = __expf(lrelu(s0 + d0));
    float ee1 = __expf(lrelu(s1 + d1));
    if (lane == 0) {
        as_[2 * (size_t)w] = s0;  as_[2 * (size_t)w + 1] = s1;
        ad_[2 * (size_t)w] = d0;  ad_[2 * (size_t)w + 1] = d1;
        dn_[2 * (size_t)w] = ee0; dn_[2 * (size_t)w + 1] = ee1;
    }
    if (valid) {
        float ee = head ? ee1 : ee0;
        ((float4*)(num_ + (size_t)w * C))[lane] =
            make_float4(v.x * ee, v.y * ee, v.z * ee, v.w * ee);
    }
}

// Fused edge pass: logit, exp, atomic denom, vector-red numerator.
template <int L>
__global__ void k_scatter(int E) {
    constexpr int C   = (L == 1) ? 128 : 64;
    constexpr int Q   = C / 4;
    constexpr int EPW = 32 / Q;
    const float *xp = XP<L>(), *as_ = AS<L>(), *ad_ = AD<L>();
    float *dn_ = DN<L>(), *num_ = NUM<L>();
    int gw   = (int)((blockIdx.x * blockDim.x + threadIdx.x) >> 5);
    int lane = threadIdx.x & 31;
    int e    = gw * EPW + lane / Q;
    int li   = lane % Q;
    if (e >= E) return;
    int s = g_src[e], d = g_dst[e];
    int head = (4 * li >= C / 2) ? 1 : 0;
    float ev = lrelu(as_[2 * (size_t)s + head] + ad_[2 * (size_t)d + head]);
    float ee = __expf(ev);
    if ((li & (Q / 2 - 1)) == 0) atomicAdd(&dn_[2 * (size_t)d + head], ee);
    float4 v = *(const float4*)(xp + (size_t)s * C + 4 * li);
    float* np = num_ + (size_t)d * C + 4 * li;
    asm volatile("red.global.add.v4.f32 [%0], {%1,%2,%3,%4};"
                 :: "l"(np), "f"(v.x * ee), "f"(v.y * ee), "f"(v.z * ee), "f"(v.w * ee)
                 : "memory");
}

// out = log_softmax(num2/dn2 + b2) over 64 channels; one warp per node.
__global__ void k_fin2(const float* __restrict__ b, float* __restrict__ out, int n) {
    int w    = (int)((blockIdx.x * blockDim.x + threadIdx.x) >> 5);
    int lane = threadIdx.x & 31;
    if (w >= n) return;
    float inv0 = 1.f / g_dn2[2 * (size_t)w], inv1 = 1.f / g_dn2[2 * (size_t)w + 1];
    int c0 = 2 * lane, c1 = c0 + 1;
    float inv = (c0 < 32) ? inv0 : inv1;
    float2 v = *(const float2*)(g_num2 + (size_t)w * 64 + c0);
    float z0 = v.x * inv + b[c0];
    float z1 = v.y * inv + b[c1];
    float m = fmaxf(z0, z1);
#pragma unroll
    for (int o = 16; o; o >>= 1) m = fmaxf(m, __shfl_xor_sync(0xffffffffu, m, o));
    float se = expf(z0 - m) + expf(z1 - m);
#pragma unroll
    for (int o = 16; o; o >>= 1) se += __shfl_xor_sync(0xffffffffu, se, o);
    float lse = m + logf(se);
    *(float2*)(out + (size_t)w * 64 + c0) = make_float2(z0 - lse, z1 - lse);
}

// ---------------- host ----------------
extern "C" void kernel_launch(void* const* d_in, const int* in_sizes, int n_in,
                              void* d_out, int out_size) {
    const float* x   = (const float*)d_in[0];
    const void*  ei  = d_in[1];
    const float* W1  = (const float*)d_in[2];
    const float* a1s = (const float*)d_in[3];
    const float* a1d = (const float*)d_in[4];
    const float* b1  = (const float*)d_in[5];
    const float* W2  = (const float*)d_in[6];
    const float* a2s = (const float*)d_in[7];
    const float* a2d = (const float*)d_in[8];
    const float* b2  = (const float*)d_in[9];
    float* out = (float*)d_out;

    int n = in_sizes[0] / 128;
    int E = in_sizes[1] / 2;

    k_detect<<<1, 256>>>((const int*)ei);
    k_convert<<<(E + 255) / 256, 256>>>(ei, E);

    // ---- layer 1 ----
    k_gemm1<<<(n + 31) / 32, 128>>>(x, W1, n);
    k_att<1><<<(n + 7) / 8, 256>>>(a1s, a1d, n);
    k_scatter<1><<<(E + 7) / 8, 256>>>(E);

    // ---- layer 2 (gemm2 fuses elu-normalize of layer-1 output) ----
    k_gemm2<<<(n + 31) / 32, 64>>>(W2, b1, n);
    k_att<2><<<(n + 7) / 8, 256>>>(a2s, a2d, n);
    k_scatter<2><<<(E + 15) / 16, 256>>>(E);
    k_fin2<<<(n + 7) / 8, 256>>>(b2, out, n);
}

// round 7
// speedup vs baseline: 1.2162x; 1.2162x over previous
#include <cuda_runtime.h>
#include <math.h>

#define NMAX 50000
#define EMAX 800000

// ---------------- scratch (static device globals; no allocation) ----------------
__device__ __align__(16) int   g_srcA[EMAX];
__device__ __align__(16) int   g_dstA[EMAX];
__device__ __align__(16) int   g_pos[EMAX];
__device__ __align__(16) int   g_ssrc[EMAX];     // src ids sorted by dst
__device__ __align__(16) int   g_cnt[NMAX + 1];
__device__ __align__(16) int   g_rowptr[NMAX + 1];
__device__ __align__(16) float g_xp1[NMAX * 128];
__device__ __align__(16) float g_h1[NMAX * 128];
__device__ __align__(16) float g_xp2[NMAX * 64];
__device__ __align__(16) float g_as1[NMAX * 2], g_ad1[NMAX * 2];
__device__ __align__(16) float g_as2[NMAX * 2], g_ad2[NMAX * 2];
__device__ int g_is64;

template <int L> __device__ __forceinline__ float* XP() { return L == 1 ? g_xp1 : g_xp2; }
template <int L> __device__ __forceinline__ float* AS() { return L == 1 ? g_as1 : g_as2; }
template <int L> __device__ __forceinline__ float* AD() { return L == 1 ? g_ad1 : g_ad2; }

__device__ __forceinline__ float lrelu(float x) { return x > 0.f ? x : 0.2f * x; }

__device__ __forceinline__ int warp_incl_scan(int v, int lane) {
#pragma unroll
    for (int o = 1; o < 32; o <<= 1) {
        int x = __shfl_up_sync(0xffffffffu, v, o);
        if (lane >= o) v += x;
    }
    return v;
}

// ---------------- CSR build ----------------

__global__ void k_detect(const int* __restrict__ ei32) {
    __shared__ int any;
    if (threadIdx.x == 0) any = 0;
    __syncthreads();
    for (int i = threadIdx.x; i < 2048; i += blockDim.x)
        if (ei32[2 * i + 1] != 0) any = 1;
    __syncthreads();
    if (threadIdx.x == 0) g_is64 = (any == 0) ? 1 : 0;
}

__global__ void k_zero(int n) {
    int i = blockIdx.x * blockDim.x + threadIdx.x;
    if (i <= n) g_cnt[i] = 0;
}

// convert indices + histogram of dst (records per-edge slot within its bucket)
__global__ void k_convert(const void* __restrict__ ei, int E) {
    int e = blockIdx.x * blockDim.x + threadIdx.x;
    if (e >= E) return;
    int s, d;
    if (g_is64) {
        const long long* p = (const long long*)ei;
        s = (int)p[e];  d = (int)p[(size_t)E + e];
    } else {
        const int* p = (const int*)ei;
        s = p[e];  d = p[(size_t)E + e];
    }
    g_srcA[e] = s;
    g_dstA[e] = d;
    g_pos[e] = atomicAdd(&g_cnt[d], 1);
}

// exclusive scan of g_cnt[0..n) -> g_rowptr; single block of 1024 threads.
__global__ void k_scan(int n, int E) {
    __shared__ int wsum[32];
    __shared__ int carry;
    int t = threadIdx.x, lane = t & 31, wid = t >> 5;
    if (t == 0) carry = 0;
    for (int base = 0; base < n; base += 1024) {
        __syncthreads();
        int c = carry;
        int v = (base + t < n) ? g_cnt[base + t] : 0;
        int incl = warp_incl_scan(v, lane);
        if (lane == 31) wsum[wid] = incl;
        __syncthreads();
        if (wid == 0) wsum[lane] = warp_incl_scan(wsum[lane], lane);
        __syncthreads();
        int off = (wid > 0) ? wsum[wid - 1] : 0;
        if (base + t < n) g_rowptr[base + t] = c + off + incl - v;
        int total = wsum[31];
        __syncthreads();
        if (t == 0) carry = c + total;
    }
    __syncthreads();
    if (t == 0) g_rowptr[n] = E;
}

__global__ void k_reorder(int E) {
    int e = blockIdx.x * blockDim.x + threadIdx.x;
    if (e >= E) return;
    int d = g_dstA[e];
    g_ssrc[g_rowptr[d] + g_pos[e]] = g_srcA[e];
}

// ---------------- dense GEMMs ----------------

template <int NCOL>
__global__ void k_gemm(const float* __restrict__ X, const float* __restrict__ W,
                       float* __restrict__ Y, int n) {
    __shared__ float Ws[64][NCOL];
    __shared__ float Xs[32][64];
    int t  = threadIdx.x;
    int n0 = blockIdx.x * 32;
    float acc[32];
#pragma unroll
    for (int i = 0; i < 32; i++) acc[i] = 0.f;
    for (int kt = 0; kt < 128; kt += 64) {
        for (int k = 0; k < 64; k++) Ws[k][t] = W[(size_t)(kt + k) * NCOL + t];
        for (int i = t; i < 32 * 64; i += NCOL) {
            int nn = i >> 6, kk = i & 63;
            int row = n0 + nn;
            Xs[nn][kk] = (row < n) ? X[(size_t)row * 128 + kt + kk] : 0.f;
        }
        __syncthreads();
#pragma unroll 4
        for (int k = 0; k < 64; k++) {
            float w = Ws[k][t];
#pragma unroll
            for (int nn = 0; nn < 32; nn++) acc[nn] += Xs[nn][k] * w;
        }
        __syncthreads();
    }
#pragma unroll
    for (int nn = 0; nn < 32; nn++) {
        int row = n0 + nn;
        if (row < n) Y[(size_t)row * NCOL + t] = acc[nn];
    }
}

// ---------------- attention dots ----------------

template <int L>
__global__ void k_att(const float* __restrict__ att_s, const float* __restrict__ att_d, int n) {
    constexpr int C = (L == 1) ? 128 : 64;
    constexpr int Q = C / 4;
    const float* xp = XP<L>();
    float *as_ = AS<L>(), *ad_ = AD<L>();
    int w    = (int)((blockIdx.x * blockDim.x + threadIdx.x) >> 5);
    int lane = threadIdx.x & 31;
    if (w >= n) return;
    bool valid = lane < Q;
    float4 v = valid ? ((const float4*)(xp + (size_t)w * C))[lane]
                     : make_float4(0.f, 0.f, 0.f, 0.f);
    int c = 4 * lane;
    float ps = 0.f, pd = 0.f;
    if (valid) {
        ps = v.x * att_s[c] + v.y * att_s[c + 1] + v.z * att_s[c + 2] + v.w * att_s[c + 3];
        pd = v.x * att_d[c] + v.y * att_d[c + 1] + v.z * att_d[c + 2] + v.w * att_d[c + 3];
    }
    int head = (c >= C / 2) ? 1 : 0;
    float s0 = head ? 0.f : ps, s1 = head ? ps : 0.f;
    float d0 = head ? 0.f : pd, d1 = head ? pd : 0.f;
#pragma unroll
    for (int o = 16; o; o >>= 1) {
        s0 += __shfl_xor_sync(0xffffffffu, s0, o);
        s1 += __shfl_xor_sync(0xffffffffu, s1, o);
        d0 += __shfl_xor_sync(0xffffffffu, d0, o);
        d1 += __shfl_xor_sync(0xffffffffu, d1, o);
    }
    if (lane == 0) {
        as_[2 * (size_t)w] = s0;  as_[2 * (size_t)w + 1] = s1;
        ad_[2 * (size_t)w] = d0;  ad_[2 * (size_t)w + 1] = d1;
    }
}

// ---------------- gather layers (register accumulation, no atomics) ----------------

// Layer 1: one warp per dst node; lane li owns float4 slot li of 128 channels.
// Emits h = elu(num/dn + b1) directly.
__global__ void k_gather1(const float* __restrict__ b1, int n) {
    int w  = (int)((blockIdx.x * blockDim.x + threadIdx.x) >> 5);
    int li = threadIdx.x & 31;
    if (w >= n) return;
    float2 ad2 = *(const float2*)(g_ad1 + 2 * (size_t)w);
    float2 a0  = *(const float2*)(g_as1 + 2 * (size_t)w);
    float eeS0 = __expf(lrelu(a0.x + ad2.x));
    float eeS1 = __expf(lrelu(a0.y + ad2.y));
    float dn0 = eeS0, dn1 = eeS1;
    float4 v = ((const float4*)(g_xp1 + (size_t)w * 128))[li];
    float eeS = (li >= 16) ? eeS1 : eeS0;
    float4 acc = make_float4(v.x * eeS, v.y * eeS, v.z * eeS, v.w * eeS);
    int beg = g_rowptr[w], end = g_rowptr[w + 1];
    for (int base = beg; base < end; base += 32) {
        int j = base + li;
        int myS = (j < end) ? g_ssrc[j] : 0;
        int cnt = min(32, end - base);
        for (int k = 0; k < cnt; k++) {
            int s = __shfl_sync(0xffffffffu, myS, k);
            float2 a = *(const float2*)(g_as1 + 2 * (size_t)s);
            float e0 = __expf(lrelu(a.x + ad2.x));
            float e1 = __expf(lrelu(a.y + ad2.y));
            dn0 += e0; dn1 += e1;
            float4 u = ((const float4*)(g_xp1 + (size_t)s * 128))[li];
            float ee = (li >= 16) ? e1 : e0;
            acc.x += u.x * ee; acc.y += u.y * ee;
            acc.z += u.z * ee; acc.w += u.w * ee;
        }
    }
    float inv = 1.f / ((li >= 16) ? dn1 : dn0);
    int c = 4 * li;
    float4 bb = *(const float4*)(b1 + c);
    float4 r;
    r.x = acc.x * inv + bb.x; r.x = r.x > 0.f ? r.x : expm1f(r.x);
    r.y = acc.y * inv + bb.y; r.y = r.y > 0.f ? r.y : expm1f(r.y);
    r.z = acc.z * inv + bb.z; r.z = r.z > 0.f ? r.z : expm1f(r.z);
    r.w = acc.w * inv + bb.w; r.w = r.w > 0.f ? r.w : expm1f(r.w);
    ((float4*)(g_h1 + (size_t)w * 128))[li] = r;
}

// Layer 2: one FULL warp per dst node; lane li owns float2 slot li of 64 channels.
// All shuffles are full-warp converged (same structure as k_gather1) — no
// divergent-mask constructs. Emits log_softmax directly to out.
__global__ void k_gather2(const float* __restrict__ b2, float* __restrict__ out, int n) {
    int w  = (int)((blockIdx.x * blockDim.x + threadIdx.x) >> 5);
    int li = threadIdx.x & 31;
    if (w >= n) return;
    float2 ad2 = *(const float2*)(g_ad2 + 2 * (size_t)w);
    float2 a0  = *(const float2*)(g_as2 + 2 * (size_t)w);
    float eeS0 = __expf(lrelu(a0.x + ad2.x));
    float eeS1 = __expf(lrelu(a0.y + ad2.y));
    float dn0 = eeS0, dn1 = eeS1;
    float2 v = ((const float2*)(g_xp2 + (size_t)w * 64))[li];
    float eeS = (li >= 16) ? eeS1 : eeS0;   // channels 2*li, 2*li+1 ; head = (2*li >= 32)
    float2 acc = make_float2(v.x * eeS, v.y * eeS);
    int beg = g_rowptr[w], end = g_rowptr[w + 1];
    for (int base = beg; base < end; base += 32) {
        int j = base + li;
        int myS = (j < end) ? g_ssrc[j] : 0;
        int cnt = min(32, end - base);
        for (int k = 0; k < cnt; k++) {
            int s = __shfl_sync(0xffffffffu, myS, k);
            float2 a = *(const float2*)(g_as2 + 2 * (size_t)s);
            float e0 = __expf(lrelu(a.x + ad2.x));
            float e1 = __expf(lrelu(a.y + ad2.y));
            dn0 += e0; dn1 += e1;
            float2 u = ((const float2*)(g_xp2 + (size_t)s * 64))[li];
            float ee = (li >= 16) ? e1 : e0;
            acc.x += u.x * ee; acc.y += u.y * ee;
        }
    }
    float inv = 1.f / ((li >= 16) ? dn1 : dn0);
    int c = 2 * li;
    float2 bb = *(const float2*)(b2 + c);
    float z0 = acc.x * inv + bb.x;
    float z1 = acc.y * inv + bb.y;
    float m = fmaxf(z0, z1);
#pragma unroll
    for (int o = 16; o; o >>= 1) m = fmaxf(m, __shfl_xor_sync(0xffffffffu, m, o));
    float se = expf(z0 - m) + expf(z1 - m);
#pragma unroll
    for (int o = 16; o; o >>= 1) se += __shfl_xor_sync(0xffffffffu, se, o);
    float lse = m + logf(se);
    *(float2*)(out + (size_t)w * 64 + c) = make_float2(z0 - lse, z1 - lse);
}

// ---------------- host ----------------
extern "C" void kernel_launch(void* const* d_in, const int* in_sizes, int n_in,
                              void* d_out, int out_size) {
    const float* x   = (const float*)d_in[0];
    const void*  ei  = d_in[1];
    const float* W1  = (const float*)d_in[2];
    const float* a1s = (const float*)d_in[3];
    const float* a1d = (const float*)d_in[4];
    const float* b1  = (const float*)d_in[5];
    const float* W2  = (const float*)d_in[6];
    const float* a2s = (const float*)d_in[7];
    const float* a2d = (const float*)d_in[8];
    const float* b2  = (const float*)d_in[9];
    float* out = (float*)d_out;

    int n = in_sizes[0] / 128;
    int E = in_sizes[1] / 2;

    float* xp1; float* xp2; float* h1;
    {
        void* p;
        cudaGetSymbolAddress(&p, g_xp1); xp1 = (float*)p;
        cudaGetSymbolAddress(&p, g_xp2); xp2 = (float*)p;
        cudaGetSymbolAddress(&p, g_h1);  h1  = (float*)p;
    }

    // CSR build
    k_detect<<<1, 256>>>((const int*)ei);
    k_zero<<<(n + 256) / 256, 256>>>(n);
    k_convert<<<(E + 255) / 256, 256>>>(ei, E);
    k_scan<<<1, 1024>>>(n, E);
    k_reorder<<<(E + 255) / 256, 256>>>(E);

    // layer 1
    k_gemm<128><<<(n + 31) / 32, 128>>>(x, W1, xp1, n);
    k_att<1><<<(n + 7) / 8, 256>>>(a1s, a1d, n);
    k_gather1<<<(n + 7) / 8, 256>>>(b1, n);

    // layer 2
    k_gemm<64><<<(n + 31) / 32, 64>>>(h1, W2, xp2, n);
    k_att<2><<<(n + 7) / 8, 256>>>(a2s, a2d, n);
    k_gather2<<<(n + 7) / 8, 256>>>(b2, out, n);
}